// round 16
// baseline (speedup 1.0000x reference)
#include <cuda_runtime.h>
#include <math.h>

// ---------------------------------------------------------------------------
// PositionEvaluator, round 15: R9 baseline (NT=256, R=16, occ=1, FFMA2 row
// pairs, CH=8 distance-1 weight ping-pong) + PRE-DUPLICATED WEIGHTS:
// a prep kernel expands every weight to u64=(w,w) in __device__ scratch, so
// FFMA2 weight operands load directly as ulonglong2 -> the 16 dup2 MOVs per
// 96 MACs (20% of issue slots) are eliminated. Same math order as R9.
// ---------------------------------------------------------------------------

#define R  16
#define G  32
#define NT 256

typedef unsigned long long u64;
union F2 { u64 u; float2 f; };

__device__ __forceinline__ u64 ffma2(u64 a, u64 b, u64 c) {
  u64 d; asm("fma.rn.f32x2 %0, %1, %2, %3;" : "=l"(d) : "l"(a), "l"(b), "l"(c)); return d;
}
__device__ __forceinline__ u64 fmul2(u64 a, u64 b) {
  u64 d; asm("mul.rn.f32x2 %0, %1, %2;" : "=l"(d) : "l"(a), "l"(b)); return d;
}
__device__ __forceinline__ u64 dup2(float w) {
  u64 d; asm("mov.b64 %0, {%1, %1};" : "=l"(d) : "f"(w)); return d;
}
__device__ __forceinline__ u64 ld2(const float* p) {
  return *reinterpret_cast<const u64*>(p);
}
__device__ __forceinline__ void st2(float* p, u64 v) {
  *reinterpret_cast<u64*>(p) = v;
}

// ---- duplicated-weight scratch (u64 per original float) -------------------
#define OFF_G1_WVH 0
#define OFF_G1_WS  8192
#define OFF_G1_WVO 57344
#define OFF_G1_WG  73728
#define OFF_G1_WD  90112
#define OFF_G2_WVH 106496
#define OFF_G2_WS  122880
#define OFF_G2_WVO 155648
#define OFF_G2_WG  172032
#define OFF_A1_WVH 188416
#define OFF_A1_WS  221184
#define OFF_A1_WVO 270336
#define OFF_A1_WG  335872
#define OFF_A1_WD  368640
#define OFF_A2_WVH 434176
#define OFF_A2_WS  450560
#define OFF_A2_WVO 499712
#define OFF_A2_WG  516096
#define OFF_A2_WD  532480
#define OFF_F_WVH  548864
#define W_TOTAL    565248

__device__ u64 g_wdup[W_TOTAL];

__global__ void dup_w(const float* w0,  const float* w1,  const float* w2,
                      const float* w3,  const float* w4,  const float* w5,
                      const float* w6,  const float* w7,  const float* w8,
                      const float* w9,  const float* w10, const float* w11,
                      const float* w12, const float* w13, const float* w14,
                      const float* w15, const float* w16, const float* w17,
                      const float* w18, const float* w19)
{
  const float* srcs[20] = {w0,w1,w2,w3,w4,w5,w6,w7,w8,w9,
                           w10,w11,w12,w13,w14,w15,w16,w17,w18,w19};
  const int ends[20] = {8192,57344,73728,90112,106496,122880,155648,172032,
                        188416,221184,270336,335872,368640,434176,450560,
                        499712,516096,532480,548864,565248};
  for (int i = blockIdx.x * blockDim.x + threadIdx.x; i < W_TOTAL;
       i += gridDim.x * blockDim.x) {
    int m = 0, base = 0;
    while (i >= ends[m]) { base = ends[m]; ++m; }
    const unsigned b = __float_as_uint(srcs[m][i - base]);
    g_wdup[i] = ((u64)b << 32) | (u64)b;
  }
}

struct SM {
  float sv[3][256][R];
  float sh[3][256][R];
  float snorm[256][R];
  float ssc[256][R];
  float so[128][R];
  float rp[3][R];
  int   nidx[R];
};

// ---------------- vector dot, dup'd weights, ping-pong ---------------------
// acc[j][i] += sum_c W[g+G*j][c] * x[i][c][pair]
template<int J, int CIN>
__device__ __forceinline__ void vdotD(const u64* __restrict__ Wd_,
                                      float (*x)[256][R],
                                      u64 (&acc)[J][3], int g, int p)
{
  constexpr int CH = (J >= 8) ? 4 : 8;   // columns per chunk
  constexpr int NU = CH / 2;             // ulonglong2 per j per chunk
  constexpr int NCH = CIN / CH;
  static_assert(NCH % 2 == 0, "NCH even");
  const ulonglong2* rowp[J];
#pragma unroll
  for (int j = 0; j < J; ++j)
    rowp[j] = reinterpret_cast<const ulonglong2*>(Wd_ + (size_t)(g + G * j) * CIN);

  ulonglong2 A[J][NU], B[J][NU];
#pragma unroll
  for (int j = 0; j < J; ++j)
#pragma unroll
    for (int q = 0; q < NU; ++q) A[j][q] = __ldg(rowp[j] + q);

#pragma unroll 1
  for (int ch = 0; ch < NCH; ch += 2) {
#pragma unroll
    for (int j = 0; j < J; ++j)
#pragma unroll
      for (int q = 0; q < NU; ++q) B[j][q] = __ldg(rowp[j] + (ch + 1) * NU + q);
    {
      u64 xv[3][CH];
#pragma unroll
      for (int t = 0; t < CH; ++t) {
        xv[0][t] = ld2(&x[0][ch * CH + t][2 * p]);
        xv[1][t] = ld2(&x[1][ch * CH + t][2 * p]);
        xv[2][t] = ld2(&x[2][ch * CH + t][2 * p]);
      }
#pragma unroll
      for (int j = 0; j < J; ++j)
#pragma unroll
        for (int q = 0; q < NU; ++q)
#pragma unroll
          for (int i = 0; i < 3; ++i) {
            acc[j][i] = ffma2(A[j][q].x, xv[i][2 * q],     acc[j][i]);
            acc[j][i] = ffma2(A[j][q].y, xv[i][2 * q + 1], acc[j][i]);
          }
    }
    const int cn = (ch + 2 < NCH) ? (ch + 2) : 0;
#pragma unroll
    for (int j = 0; j < J; ++j)
#pragma unroll
      for (int q = 0; q < NU; ++q) A[j][q] = __ldg(rowp[j] + cn * NU + q);
    {
      u64 xv[3][CH];
#pragma unroll
      for (int t = 0; t < CH; ++t) {
        xv[0][t] = ld2(&x[0][(ch + 1) * CH + t][2 * p]);
        xv[1][t] = ld2(&x[1][(ch + 1) * CH + t][2 * p]);
        xv[2][t] = ld2(&x[2][(ch + 1) * CH + t][2 * p]);
      }
#pragma unroll
      for (int j = 0; j < J; ++j)
#pragma unroll
        for (int q = 0; q < NU; ++q)
#pragma unroll
          for (int i = 0; i < 3; ++i) {
            acc[j][i] = ffma2(B[j][q].x, xv[i][2 * q],     acc[j][i]);
            acc[j][i] = ffma2(B[j][q].y, xv[i][2 * q + 1], acc[j][i]);
          }
    }
  }
}

// ---------------- scalar dot segment, dup'd weights, ping-pong -------------
template<int J, int K, int OFF, int Kseg>
__device__ __forceinline__ void sdotD(const u64* __restrict__ Wd_,
                                      float (*x)[R],
                                      u64 (&acc)[J], int g, int p)
{
  constexpr int CH = (J >= 8) ? 4 : 8;
  constexpr int NU = CH / 2;
  constexpr int NCH = Kseg / CH;
  static_assert(NCH % 2 == 0, "NCH even");
  const ulonglong2* rowp[J];
#pragma unroll
  for (int j = 0; j < J; ++j)
    rowp[j] = reinterpret_cast<const ulonglong2*>(Wd_ + (size_t)(g + G * j) * K + OFF);

  ulonglong2 A[J][NU], B[J][NU];
#pragma unroll
  for (int j = 0; j < J; ++j)
#pragma unroll
    for (int q = 0; q < NU; ++q) A[j][q] = __ldg(rowp[j] + q);

#pragma unroll 1
  for (int ch = 0; ch < NCH; ch += 2) {
#pragma unroll
    for (int j = 0; j < J; ++j)
#pragma unroll
      for (int q = 0; q < NU; ++q) B[j][q] = __ldg(rowp[j] + (ch + 1) * NU + q);
    {
      u64 xv[CH];
#pragma unroll
      for (int t = 0; t < CH; ++t) xv[t] = ld2(&x[ch * CH + t][2 * p]);
#pragma unroll
      for (int j = 0; j < J; ++j)
#pragma unroll
        for (int q = 0; q < NU; ++q) {
          acc[j] = ffma2(A[j][q].x, xv[2 * q],     acc[j]);
          acc[j] = ffma2(A[j][q].y, xv[2 * q + 1], acc[j]);
        }
    }
    const int cn = (ch + 2 < NCH) ? (ch + 2) : 0;
#pragma unroll
    for (int j = 0; j < J; ++j)
#pragma unroll
      for (int q = 0; q < NU; ++q) A[j][q] = __ldg(rowp[j] + cn * NU + q);
    {
      u64 xv[CH];
#pragma unroll
      for (int t = 0; t < CH; ++t) xv[t] = ld2(&x[(ch + 1) * CH + t][2 * p]);
#pragma unroll
      for (int j = 0; j < J; ++j)
#pragma unroll
        for (int q = 0; q < NU; ++q) {
          acc[j] = ffma2(B[j][q].x, xv[2 * q],     acc[j]);
          acc[j] = ffma2(B[j][q].y, xv[2 * q + 1], acc[j]);
        }
    }
  }
}

// ---------------- stage building blocks ----------------

template<int OUT, int CIN, bool NORM>
__device__ __forceinline__ void matvec_v(const u64* __restrict__ Wd_,
                                         float (*x)[256][R],
                                         float (*y)[256][R],
                                         float (*nrm)[R],
                                         int g, int p)
{
  constexpr int J = OUT / G;
  u64 acc[J][3];
#pragma unroll
  for (int j = 0; j < J; ++j) { acc[j][0] = 0ull; acc[j][1] = 0ull; acc[j][2] = 0ull; }
  vdotD<J, CIN>(Wd_, x, acc, g, p);
#pragma unroll
  for (int j = 0; j < J; ++j) {
    const int o = g + G * j;
    st2(&y[0][o][2 * p], acc[j][0]);
    st2(&y[1][o][2 * p], acc[j][1]);
    st2(&y[2][o][2 * p], acc[j][2]);
    if (NORM) {
      u64 s = fmul2(acc[j][0], acc[j][0]);
      s = ffma2(acc[j][1], acc[j][1], s);
      s = ffma2(acc[j][2], acc[j][2], s);
      F2 t; t.u = s;
      F2 n; n.f.x = sqrtf(t.f.x); n.f.y = sqrtf(t.f.y);
      st2(&nrm[o][2 * p], n.u);
    }
  }
}

template<int OUT, int K1, int K2>
__device__ __forceinline__ void matvec_s2(const u64* __restrict__ Wd_,
                                          float (*x1)[R], float (*x2)[R],
                                          float (*y)[R], int g, int p)
{
  constexpr int J = OUT / G;
  u64 acc[J];
#pragma unroll
  for (int j = 0; j < J; ++j) acc[j] = 0ull;
  sdotD<J, K1 + K2, 0,  K1>(Wd_, x1, acc, g, p);
  sdotD<J, K1 + K2, K1, K2>(Wd_, x2, acc, g, p);
#pragma unroll
  for (int j = 0; j < J; ++j) st2(&y[g + G * j][2 * p], acc[j]);
}

template<int OUT, int H, int KG>
__device__ __forceinline__ void gated_outv(const u64* __restrict__ Wvo_,
                                           const u64* __restrict__ Wg_,
                                           const float* __restrict__ bg,
                                           float (*vh)[256][R],
                                           float (*so)[R],
                                           float (*v)[256][R],
                                           int g, int p)
{
  constexpr int J = OUT / G;
  u64 gacc[J];
#pragma unroll
  for (int j = 0; j < J; ++j) gacc[j] = 0ull;
  sdotD<J, KG, 0, KG>(Wg_, so, gacc, g, p);
  u64 gate[J];
#pragma unroll
  for (int j = 0; j < J; ++j) {
    const float b = __ldg(&bg[g + G * j]);
    F2 t; t.u = gacc[j];
    F2 gt;
    gt.f.x = 1.f / (1.f + __expf(-(t.f.x + b)));
    gt.f.y = 1.f / (1.f + __expf(-(t.f.y + b)));
    gate[j] = gt.u;
  }
  u64 acc[J][3];
#pragma unroll
  for (int j = 0; j < J; ++j) { acc[j][0] = 0ull; acc[j][1] = 0ull; acc[j][2] = 0ull; }
  vdotD<J, H>(Wvo_, vh, acc, g, p);
#pragma unroll
  for (int j = 0; j < J; ++j) {
    const int o = g + G * j;
    st2(&v[0][o][2 * p], fmul2(gate[j], acc[j][0]));
    st2(&v[1][o][2 * p], fmul2(gate[j], acc[j][1]));
    st2(&v[2][o][2 * p], fmul2(gate[j], acc[j][2]));
  }
}

template<int OUT, bool LEAKY>
__device__ __forceinline__ void scalar_act(float (*so)[R], float (*dst)[R], int g, int p)
{
  constexpr int J = OUT / G;
#pragma unroll
  for (int j = 0; j < J; ++j) {
    const int o = g + G * j;
    F2 t; t.u = ld2(&so[o][2 * p]);
    if (LEAKY) {
      t.f.x = t.f.x >= 0.f ? t.f.x : 0.01f * t.f.x;
      t.f.y = t.f.y >= 0.f ? t.f.y : 0.01f * t.f.y;
    }
    st2(&dst[o][2 * p], t.u);
  }
}

template<int OUT>
__device__ __forceinline__ void vnleaky_ew(float (*x)[256][R], float (*d)[256][R], int g, int p)
{
  constexpr int J = OUT / G;
#pragma unroll
  for (int j = 0; j < J; ++j) {
    const int o = g + G * j;
    F2 x0, x1, x2, d0, d1, d2;
    x0.u = ld2(&x[0][o][2 * p]); x1.u = ld2(&x[1][o][2 * p]); x2.u = ld2(&x[2][o][2 * p]);
    d0.u = ld2(&d[0][o][2 * p]); d1.u = ld2(&d[1][o][2 * p]); d2.u = ld2(&d[2][o][2 * p]);
    u64 dotu = fmul2(x0.u, d0.u); dotu = ffma2(x1.u, d1.u, dotu); dotu = ffma2(x2.u, d2.u, dotu);
    u64 dsqu = fmul2(d0.u, d0.u); dsqu = ffma2(d1.u, d1.u, dsqu); dsqu = ffma2(d2.u, d2.u, dsqu);
    F2 dot, dsq; dot.u = dotu; dsq.u = dsqu;
    F2 o0, o1, o2;
#pragma unroll
    for (int h = 0; h < 2; ++h) {
      const float dt = h ? dot.f.y : dot.f.x;
      const float ds = h ? dsq.f.y : dsq.f.x;
      const float xa = h ? x0.f.y : x0.f.x;
      const float xb = h ? x1.f.y : x1.f.x;
      const float xc = h ? x2.f.y : x2.f.x;
      const float da = h ? d0.f.y : d0.f.x;
      const float db = h ? d1.f.y : d1.f.x;
      const float dc = h ? d2.f.y : d2.f.x;
      const float t = dt / (ds + 1e-6f);
      const bool pos = (dt >= 0.f);
      const float na = pos ? xa : (xa - t * da);
      const float nb = pos ? xb : (xb - t * db);
      const float nc = pos ? xc : (xc - t * dc);
      const float ra = 0.2f * xa + 0.8f * na;
      const float rb = 0.2f * xb + 0.8f * nb;
      const float rc = 0.2f * xc + 0.8f * nc;
      if (h) { o0.f.y = ra; o1.f.y = rb; o2.f.y = rc; }
      else   { o0.f.x = ra; o1.f.x = rb; o2.f.x = rc; }
    }
    st2(&x[0][o][2 * p], o0.u);
    st2(&x[1][o][2 * p], o1.u);
    st2(&x[2][o][2 * p], o2.u);
  }
}

__global__ __launch_bounds__(NT, 1)
void pe_kernel(const float* __restrict__ h_sca, const float* __restrict__ h_vec,
               const float* __restrict__ pos_compose, const float* __restrict__ pos,
               const float* __restrict__ g1_bg, const float* __restrict__ g2_bg,
               const float* __restrict__ a1_bg, const float* __restrict__ a2_bg,
               const float* __restrict__ f_Ws,
               const int* __restrict__ idx_focal,
               float* __restrict__ out, int F)
{
  extern __shared__ char smraw[];
  SM& S = *reinterpret_cast<SM*>(smraw);
  const int tid = threadIdx.x;
  const int g = tid >> 3;    // channel group 0..31
  const int p = tid & 7;     // row pair     0..7
  const int row0 = blockIdx.x * R;

  if (tid < R) {
    const int row = row0 + tid;
    S.nidx[tid] = (row < F) ? idx_focal[row] : 0;
  }
  __syncthreads();

  if (tid < 3 * R) {
    const int rr = tid / 3, i = tid % 3;
    const int row = row0 + rr;
    const int n = S.nidx[rr];
    const float pv = (row < F) ? pos[(size_t)row * 3 + i] : 0.f;
    S.rp[i][rr] = pv - pos_compose[(size_t)n * 3 + i];
  }

  for (int rr = 0; rr < R; ++rr) {
    const size_t n = (size_t)S.nidx[rr];
    S.ssc[tid][rr] = __ldg(&h_sca[n * 256 + tid]);
    if (tid < 192) S.sv[tid % 3][tid / 3][rr] = __ldg(&h_vec[n * 192 + tid]);
  }
  __syncthreads();

  // ================= g1: gv_perceptron =================
  matvec_v<128, 64, true>(g_wdup + OFF_G1_WVH, S.sv, S.sh, S.snorm, g, p);
  __syncthreads();
  matvec_s2<128, 128, 256>(g_wdup + OFF_G1_WS, S.snorm, S.ssc, S.so, g, p);
  __syncthreads();
  gated_outv<128, 128, 128>(g_wdup + OFF_G1_WVO, g_wdup + OFF_G1_WG, g1_bg,
                            S.sh, S.so, S.sv, g, p);
  scalar_act<128, true>(S.so, S.ssc, g, p);
  __syncthreads();
  matvec_v<128, 128, false>(g_wdup + OFF_G1_WD, S.sv, S.sh, S.snorm, g, p);
  __syncthreads();
  vnleaky_ew<128>(S.sv, S.sh, g, p);
  __syncthreads();

  // ================= g2: gv_linear =================
  matvec_v<128, 128, true>(g_wdup + OFF_G2_WVH, S.sv, S.sh, S.snorm, g, p);
  __syncthreads();
  matvec_s2<128, 128, 128>(g_wdup + OFF_G2_WS, S.snorm, S.ssc, S.so, g, p);
  __syncthreads();
  gated_outv<128, 128, 128>(g_wdup + OFF_G2_WVO, g_wdup + OFF_G2_WG, g2_bg,
                            S.sh, S.so, S.sv, g, p);
  scalar_act<128, false>(S.so, S.ssc, g, p);
  __syncthreads();

  // ================= a1: gv_perceptron =================
  matvec_v<256, 128, true>(g_wdup + OFF_A1_WVH, S.sv, S.sh, S.snorm, g, p);
  __syncthreads();
  matvec_s2<128, 256, 128>(g_wdup + OFF_A1_WS, S.snorm, S.ssc, S.so, g, p);
  __syncthreads();
  gated_outv<256, 256, 128>(g_wdup + OFF_A1_WVO, g_wdup + OFF_A1_WG, a1_bg,
                            S.sh, S.so, S.sv, g, p);
  scalar_act<128, true>(S.so, S.ssc, g, p);
  __syncthreads();
  matvec_v<256, 256, false>(g_wdup + OFF_A1_WD, S.sv, S.sh, S.snorm, g, p);
  __syncthreads();
  vnleaky_ew<256>(S.sv, S.sh, g, p);
  __syncthreads();

  // ===== split: inner = <x_vec2, relpos> -> ssc[128..255] =====
  {
    const u64 rp0 = ld2(&S.rp[0][2 * p]);
    const u64 rp1 = ld2(&S.rp[1][2 * p]);
    const u64 rp2 = ld2(&S.rp[2][2 * p]);
#pragma unroll
    for (int j = 0; j < 4; ++j) {
      const int o = g + G * j;
      u64 acc = fmul2(ld2(&S.sv[0][128 + o][2 * p]), rp0);
      acc = ffma2(ld2(&S.sv[1][128 + o][2 * p]), rp1, acc);
      acc = ffma2(ld2(&S.sv[2][128 + o][2 * p]), rp2, acc);
      st2(&S.ssc[128 + o][2 * p], acc);
    }
  }
  __syncthreads();

  // ================= a2: gv_perceptron =================
  matvec_v<128, 128, true>(g_wdup + OFF_A2_WVH, S.sv, S.sh, S.snorm, g, p);
  __syncthreads();
  matvec_s2<128, 128, 256>(g_wdup + OFF_A2_WS, S.snorm, S.ssc, S.so, g, p);
  __syncthreads();
  gated_outv<128, 128, 128>(g_wdup + OFF_A2_WVO, g_wdup + OFF_A2_WG, a2_bg,
                            S.sh, S.so, S.sv, g, p);
  scalar_act<128, true>(S.so, S.ssc, g, p);
  __syncthreads();
  matvec_v<128, 128, false>(g_wdup + OFF_A2_WD, S.sv, S.sh, S.snorm, g, p);
  __syncthreads();
  vnleaky_ew<128>(S.sv, S.sh, g, p);
  __syncthreads();

  // ================= final =================
  matvec_v<128, 128, true>(g_wdup + OFF_F_WVH, S.sv, S.sh, S.snorm, g, p);
  __syncthreads();
  {
    u64 acc = 0ull;
#pragma unroll
    for (int kk = 0; kk < 8; ++kk) {
      const int k = g * 8 + kk;
      const u64 xv = (k < 128) ? ld2(&S.snorm[k][2 * p]) : ld2(&S.ssc[k - 128][2 * p]);
      acc = ffma2(dup2(__ldg(&f_Ws[k])), xv, acc);
    }
    st2(&S.so[g][2 * p], acc);
  }
  __syncthreads();
  if (tid < R) {
    const int row = row0 + tid;
    float acc = 0.f;
#pragma unroll
    for (int gg = 0; gg < G; ++gg) acc += S.so[gg][tid];
    if (row < F) out[row] = acc;
  }
}

extern "C" void kernel_launch(void* const* d_in, const int* in_sizes, int n_in,
                              void* d_out, int out_size)
{
  const float* h_sca       = (const float*)d_in[0];
  const float* h_vec       = (const float*)d_in[1];
  const float* pos_compose = (const float*)d_in[2];
  const float* pos         = (const float*)d_in[3];
  const float* g1_Wvh = (const float*)d_in[4];
  const float* g1_Ws  = (const float*)d_in[5];
  const float* g1_Wvo = (const float*)d_in[6];
  const float* g1_Wg  = (const float*)d_in[7];
  const float* g1_bg  = (const float*)d_in[8];
  const float* g1_Wd  = (const float*)d_in[9];
  const float* g2_Wvh = (const float*)d_in[10];
  const float* g2_Ws  = (const float*)d_in[11];
  const float* g2_Wvo = (const float*)d_in[12];
  const float* g2_Wg  = (const float*)d_in[13];
  const float* g2_bg  = (const float*)d_in[14];
  const float* a1_Wvh = (const float*)d_in[15];
  const float* a1_Ws  = (const float*)d_in[16];
  const float* a1_Wvo = (const float*)d_in[17];
  const float* a1_Wg  = (const float*)d_in[18];
  const float* a1_bg  = (const float*)d_in[19];
  const float* a1_Wd  = (const float*)d_in[20];
  const float* a2_Wvh = (const float*)d_in[21];
  const float* a2_Ws  = (const float*)d_in[22];
  const float* a2_Wvo = (const float*)d_in[23];
  const float* a2_Wg  = (const float*)d_in[24];
  const float* a2_bg  = (const float*)d_in[25];
  const float* a2_Wd  = (const float*)d_in[26];
  const float* f_Wvh  = (const float*)d_in[27];
  const float* f_Ws   = (const float*)d_in[28];
  const int*   idx_focal = (const int*)d_in[29];

  const int F = in_sizes[3] / 3;   // pos is (F, 3)
  const int grid = (F + R - 1) / R;

  // 1) expand weights into duplicated-lane scratch (graph-capturable)
  dup_w<<<1024, 256>>>(g1_Wvh, g1_Ws, g1_Wvo, g1_Wg, g1_Wd,
                       g2_Wvh, g2_Ws, g2_Wvo, g2_Wg,
                       a1_Wvh, a1_Ws, a1_Wvo, a1_Wg, a1_Wd,
                       a2_Wvh, a2_Ws, a2_Wvo, a2_Wg, a2_Wd,
                       f_Wvh);

  // 2) main fused kernel
  cudaFuncSetAttribute(pe_kernel, cudaFuncAttributeMaxDynamicSharedMemorySize,
                       (int)sizeof(SM));
  pe_kernel<<<grid, NT, sizeof(SM)>>>(
      h_sca, h_vec, pos_compose, pos,
      g1_bg, g2_bg, a1_bg, a2_bg, f_Ws, idx_focal,
      (float*)d_out, F);
}

// round 17
// speedup vs baseline: 1.3812x; 1.3812x over previous
#include <cuda_runtime.h>
#include <math.h>

// ---------------------------------------------------------------------------
// PositionEvaluator, round 16: R9 winner (NT=256, R=16, occ=1, FFMA2 row
// pairs, CH=8 dist-1 weight ping-pong) with ONE change: activations repacked
// as float4 = {c@2p, c@2p+1, c+1@2p, c+1@2p+1} so each xv fetch is a single
// LDS.128 yielding TWO columns -> LDS instruction count halves at constant
// bytes/LDG/registers. Targets the measured L1tex ceiling (78% at R9; every
// failed variant pushed it to 84-90%).
// ---------------------------------------------------------------------------

#define R  16
#define G  32
#define NT 256

typedef unsigned long long u64;
union F2 { u64 u; float2 f; };

__device__ __forceinline__ u64 ffma2(u64 a, u64 b, u64 c) {
  u64 d; asm("fma.rn.f32x2 %0, %1, %2, %3;" : "=l"(d) : "l"(a), "l"(b), "l"(c)); return d;
}
__device__ __forceinline__ u64 fmul2(u64 a, u64 b) {
  u64 d; asm("mul.rn.f32x2 %0, %1, %2;" : "=l"(d) : "l"(a), "l"(b)); return d;
}
__device__ __forceinline__ u64 dup2(float w) {
  u64 d; asm("mov.b64 %0, {%1, %1};" : "=l"(d) : "f"(w)); return d;
}
__device__ __forceinline__ u64 ld2(const float* p) {
  return *reinterpret_cast<const u64*>(p);
}

struct SM {
  float4 sv[3][128][8];   // [comp][colpair][rowpair] {c@2p, c@2p+1, c+1@2p, c+1@2p+1}
  float4 sh[3][128][8];   // vh / d scratch, same packing
  float4 sn[128][8];      // norms (256 ch)
  float4 ss[128][8];      // scalar activations (256 ch)
  float4 so[64][8];       // out_s (128 ch) / final scratch
  float  rp[3][R];
  int    nidx[R];
};

// packed accessors -----------------------------------------------------------
__device__ __forceinline__ u64 uget(const float4 (*a)[8], int c, int p) {
  return reinterpret_cast<const u64*>(&a[c >> 1][p])[c & 1];
}
__device__ __forceinline__ void uset(float4 (*a)[8], int c, int p, u64 v) {
  reinterpret_cast<u64*>(&a[c >> 1][p])[c & 1] = v;
}
__device__ __forceinline__ ulonglong2 u2get(const float4 (*a)[8], int cp, int p) {
  return *reinterpret_cast<const ulonglong2*>(&a[cp][p]);
}

// ---------------- vector dot with weight ping-pong (packed xv) -------------
// acc[j][i] += sum_c W[g+G*j][c] * x[i][c][pair]
template<int J, int CIN>
__device__ __forceinline__ void vdot_all(const float* __restrict__ W,
                                         const float4 (*x)[128][8],
                                         u64 (&acc)[J][3], int g, int p)
{
  constexpr int CH = (J >= 8) ? 4 : 8;   // columns per half-chunk
  constexpr int NF = CH / 4;             // float4 weights per j per half
  constexpr int NX = CH / 2;             // ulonglong2 xv loads per comp per half
  static_assert(CIN % (2 * CH) == 0, "CIN mult");
  const float4* rowp[J];
#pragma unroll
  for (int j = 0; j < J; ++j)
    rowp[j] = reinterpret_cast<const float4*>(W + (size_t)(g + G * j) * CIN);

  float4 A[J][NF], B[J][NF];
#pragma unroll
  for (int j = 0; j < J; ++j)
#pragma unroll
    for (int q = 0; q < NF; ++q) A[j][q] = __ldg(rowp[j] + q);

#pragma unroll 1
  for (int c = 0; c < CIN; c += 2 * CH) {
#pragma unroll
    for (int j = 0; j < J; ++j)
#pragma unroll
      for (int q = 0; q < NF; ++q)
        B[j][q] = __ldg(rowp[j] + (c + CH) / 4 + q);
    {
      ulonglong2 xv[3][NX];
#pragma unroll
      for (int i = 0; i < 3; ++i)
#pragma unroll
        for (int cc = 0; cc < NX; ++cc) xv[i][cc] = u2get(x[i], c / 2 + cc, p);
#pragma unroll
      for (int j = 0; j < J; ++j)
#pragma unroll
        for (int q = 0; q < NF; ++q) {
          const u64 w0 = dup2(A[j][q].x), w1 = dup2(A[j][q].y);
          const u64 w2 = dup2(A[j][q].z), w3 = dup2(A[j][q].w);
#pragma unroll
          for (int i = 0; i < 3; ++i) {
            acc[j][i] = ffma2(w0, xv[i][2 * q].x,     acc[j][i]);
            acc[j][i] = ffma2(w1, xv[i][2 * q].y,     acc[j][i]);
            acc[j][i] = ffma2(w2, xv[i][2 * q + 1].x, acc[j][i]);
            acc[j][i] = ffma2(w3, xv[i][2 * q + 1].y, acc[j][i]);
          }
        }
    }
    const int cn = (c + 2 * CH < CIN) ? (c + 2 * CH) : 0;
#pragma unroll
    for (int j = 0; j < J; ++j)
#pragma unroll
      for (int q = 0; q < NF; ++q)
        A[j][q] = __ldg(rowp[j] + cn / 4 + q);
    {
      ulonglong2 xv[3][NX];
#pragma unroll
      for (int i = 0; i < 3; ++i)
#pragma unroll
        for (int cc = 0; cc < NX; ++cc) xv[i][cc] = u2get(x[i], (c + CH) / 2 + cc, p);
#pragma unroll
      for (int j = 0; j < J; ++j)
#pragma unroll
        for (int q = 0; q < NF; ++q) {
          const u64 w0 = dup2(B[j][q].x), w1 = dup2(B[j][q].y);
          const u64 w2 = dup2(B[j][q].z), w3 = dup2(B[j][q].w);
#pragma unroll
          for (int i = 0; i < 3; ++i) {
            acc[j][i] = ffma2(w0, xv[i][2 * q].x,     acc[j][i]);
            acc[j][i] = ffma2(w1, xv[i][2 * q].y,     acc[j][i]);
            acc[j][i] = ffma2(w2, xv[i][2 * q + 1].x, acc[j][i]);
            acc[j][i] = ffma2(w3, xv[i][2 * q + 1].y, acc[j][i]);
          }
        }
    }
  }
}

// ---------------- scalar dot segment with weight ping-pong (packed xv) -----
template<int J, int K, int OFF, int Kseg>
__device__ __forceinline__ void sdot_seg(const float* __restrict__ W,
                                         const float4 (*x)[8],
                                         u64 (&acc)[J], int g, int p)
{
  constexpr int CH = (J >= 8) ? 8 : 16;
  constexpr int NF = CH / 4;
  constexpr int NX = CH / 2;
  static_assert(Kseg % (2 * CH) == 0, "Kseg mult");
  static_assert(OFF % 2 == 0, "OFF even");
  const float4* rowp[J];
#pragma unroll
  for (int j = 0; j < J; ++j)
    rowp[j] = reinterpret_cast<const float4*>(W + (size_t)(g + G * j) * K + OFF);

  float4 A[J][NF], B[J][NF];
#pragma unroll
  for (int j = 0; j < J; ++j)
#pragma unroll
    for (int q = 0; q < NF; ++q) A[j][q] = __ldg(rowp[j] + q);

#pragma unroll 1
  for (int k = 0; k < Kseg; k += 2 * CH) {
#pragma unroll
    for (int j = 0; j < J; ++j)
#pragma unroll
      for (int q = 0; q < NF; ++q)
        B[j][q] = __ldg(rowp[j] + (k + CH) / 4 + q);
    {
      ulonglong2 xv[NX];
#pragma unroll
      for (int cc = 0; cc < NX; ++cc) xv[cc] = u2get(x, k / 2 + cc, p);
#pragma unroll
      for (int j = 0; j < J; ++j)
#pragma unroll
        for (int q = 0; q < NF; ++q) {
          acc[j] = ffma2(dup2(A[j][q].x), xv[2 * q].x,     acc[j]);
          acc[j] = ffma2(dup2(A[j][q].y), xv[2 * q].y,     acc[j]);
          acc[j] = ffma2(dup2(A[j][q].z), xv[2 * q + 1].x, acc[j]);
          acc[j] = ffma2(dup2(A[j][q].w), xv[2 * q + 1].y, acc[j]);
        }
    }
    const int kn = (k + 2 * CH < Kseg) ? (k + 2 * CH) : 0;
#pragma unroll
    for (int j = 0; j < J; ++j)
#pragma unroll
      for (int q = 0; q < NF; ++q)
        A[j][q] = __ldg(rowp[j] + kn / 4 + q);
    {
      ulonglong2 xv[NX];
#pragma unroll
      for (int cc = 0; cc < NX; ++cc) xv[cc] = u2get(x, (k + CH) / 2 + cc, p);
#pragma unroll
      for (int j = 0; j < J; ++j)
#pragma unroll
        for (int q = 0; q < NF; ++q) {
          acc[j] = ffma2(dup2(B[j][q].x), xv[2 * q].x,     acc[j]);
          acc[j] = ffma2(dup2(B[j][q].y), xv[2 * q].y,     acc[j]);
          acc[j] = ffma2(dup2(B[j][q].z), xv[2 * q + 1].x, acc[j]);
          acc[j] = ffma2(dup2(B[j][q].w), xv[2 * q + 1].y, acc[j]);
        }
    }
  }
}

// ---------------- stage building blocks ----------------

template<int OUT, int CIN, bool NORM>
__device__ __forceinline__ void matvec_v(const float* __restrict__ W,
                                         const float4 (*x)[128][8],
                                         float4 (*y)[128][8],
                                         float4 (*nrm)[8],
                                         int g, int p)
{
  constexpr int J = OUT / G;
  u64 acc[J][3];
#pragma unroll
  for (int j = 0; j < J; ++j) { acc[j][0] = 0ull; acc[j][1] = 0ull; acc[j][2] = 0ull; }
  vdot_all<J, CIN>(W, x, acc, g, p);
#pragma unroll
  for (int j = 0; j < J; ++j) {
    const int o = g + G * j;
    uset(y[0], o, p, acc[j][0]);
    uset(y[1], o, p, acc[j][1]);
    uset(y[2], o, p, acc[j][2]);
    if (NORM) {
      u64 s = fmul2(acc[j][0], acc[j][0]);
      s = ffma2(acc[j][1], acc[j][1], s);
      s = ffma2(acc[j][2], acc[j][2], s);
      F2 t; t.u = s;
      F2 n; n.f.x = sqrtf(t.f.x); n.f.y = sqrtf(t.f.y);
      uset(nrm, o, p, n.u);
    }
  }
}

template<int OUT, int K1, int K2>
__device__ __forceinline__ void matvec_s2(const float* __restrict__ W,
                                          const float4 (*x1)[8], const float4 (*x2)[8],
                                          float4 (*y)[8], int g, int p)
{
  constexpr int J = OUT / G;
  u64 acc[J];
#pragma unroll
  for (int j = 0; j < J; ++j) acc[j] = 0ull;
  sdot_seg<J, K1 + K2, 0,  K1>(W, x1, acc, g, p);
  sdot_seg<J, K1 + K2, K1, K2>(W, x2, acc, g, p);
#pragma unroll
  for (int j = 0; j < J; ++j) uset(y, g + G * j, p, acc[j]);
}

template<int OUT, int H, int KG>
__device__ __forceinline__ void gated_outv(const float* __restrict__ Wvo,
                                           const float* __restrict__ Wg,
                                           const float* __restrict__ bg,
                                           const float4 (*vh)[128][8],
                                           const float4 (*so)[8],
                                           float4 (*v)[128][8],
                                           int g, int p)
{
  constexpr int J = OUT / G;
  u64 gacc[J];
#pragma unroll
  for (int j = 0; j < J; ++j) gacc[j] = 0ull;
  sdot_seg<J, KG, 0, KG>(Wg, so, gacc, g, p);
  u64 gate[J];
#pragma unroll
  for (int j = 0; j < J; ++j) {
    const float b = __ldg(&bg[g + G * j]);
    F2 t; t.u = gacc[j];
    F2 gt;
    gt.f.x = 1.f / (1.f + __expf(-(t.f.x + b)));
    gt.f.y = 1.f / (1.f + __expf(-(t.f.y + b)));
    gate[j] = gt.u;
  }
  u64 acc[J][3];
#pragma unroll
  for (int j = 0; j < J; ++j) { acc[j][0] = 0ull; acc[j][1] = 0ull; acc[j][2] = 0ull; }
  vdot_all<J, H>(Wvo, vh, acc, g, p);
#pragma unroll
  for (int j = 0; j < J; ++j) {
    const int o = g + G * j;
    uset(v[0], o, p, fmul2(gate[j], acc[j][0]));
    uset(v[1], o, p, fmul2(gate[j], acc[j][1]));
    uset(v[2], o, p, fmul2(gate[j], acc[j][2]));
  }
}

template<int OUT, bool LEAKY>
__device__ __forceinline__ void scalar_act(const float4 (*so)[8], float4 (*dst)[8],
                                           int g, int p)
{
  constexpr int J = OUT / G;
#pragma unroll
  for (int j = 0; j < J; ++j) {
    const int o = g + G * j;
    F2 t; t.u = uget(so, o, p);
    if (LEAKY) {
      t.f.x = t.f.x >= 0.f ? t.f.x : 0.01f * t.f.x;
      t.f.y = t.f.y >= 0.f ? t.f.y : 0.01f * t.f.y;
    }
    uset(dst, o, p, t.u);
  }
}

template<int OUT>
__device__ __forceinline__ void vnleaky_ew(float4 (*x)[128][8], const float4 (*d)[128][8],
                                           int g, int p)
{
  constexpr int J = OUT / G;
#pragma unroll
  for (int j = 0; j < J; ++j) {
    const int o = g + G * j;
    F2 x0, x1, x2, d0, d1, d2;
    x0.u = uget(x[0], o, p); x1.u = uget(x[1], o, p); x2.u = uget(x[2], o, p);
    d0.u = uget(d[0], o, p); d1.u = uget(d[1], o, p); d2.u = uget(d[2], o, p);
    u64 dotu = fmul2(x0.u, d0.u); dotu = ffma2(x1.u, d1.u, dotu); dotu = ffma2(x2.u, d2.u, dotu);
    u64 dsqu = fmul2(d0.u, d0.u); dsqu = ffma2(d1.u, d1.u, dsqu); dsqu = ffma2(d2.u, d2.u, dsqu);
    F2 dot, dsq; dot.u = dotu; dsq.u = dsqu;
    F2 o0, o1, o2;
#pragma unroll
    for (int h = 0; h < 2; ++h) {
      const float dt = h ? dot.f.y : dot.f.x;
      const float ds = h ? dsq.f.y : dsq.f.x;
      const float xa = h ? x0.f.y : x0.f.x;
      const float xb = h ? x1.f.y : x1.f.x;
      const float xc = h ? x2.f.y : x2.f.x;
      const float da = h ? d0.f.y : d0.f.x;
      const float db = h ? d1.f.y : d1.f.x;
      const float dc = h ? d2.f.y : d2.f.x;
      const float t = dt / (ds + 1e-6f);
      const bool pos = (dt >= 0.f);
      const float na = pos ? xa : (xa - t * da);
      const float nb = pos ? xb : (xb - t * db);
      const float nc = pos ? xc : (xc - t * dc);
      const float ra = 0.2f * xa + 0.8f * na;
      const float rb = 0.2f * xb + 0.8f * nb;
      const float rc = 0.2f * xc + 0.8f * nc;
      if (h) { o0.f.y = ra; o1.f.y = rb; o2.f.y = rc; }
      else   { o0.f.x = ra; o1.f.x = rb; o2.f.x = rc; }
    }
    uset(x[0], o, p, o0.u);
    uset(x[1], o, p, o1.u);
    uset(x[2], o, p, o2.u);
  }
}

__global__ __launch_bounds__(NT, 1)
void pe_kernel(const float* __restrict__ h_sca, const float* __restrict__ h_vec,
               const float* __restrict__ pos_compose, const float* __restrict__ pos,
               const float* __restrict__ g1_Wvh, const float* __restrict__ g1_Ws,
               const float* __restrict__ g1_Wvo, const float* __restrict__ g1_Wg,
               const float* __restrict__ g1_bg,  const float* __restrict__ g1_Wd,
               const float* __restrict__ g2_Wvh, const float* __restrict__ g2_Ws,
               const float* __restrict__ g2_Wvo, const float* __restrict__ g2_Wg,
               const float* __restrict__ g2_bg,
               const float* __restrict__ a1_Wvh, const float* __restrict__ a1_Ws,
               const float* __restrict__ a1_Wvo, const float* __restrict__ a1_Wg,
               const float* __restrict__ a1_bg,  const float* __restrict__ a1_Wd,
               const float* __restrict__ a2_Wvh, const float* __restrict__ a2_Ws,
               const float* __restrict__ a2_Wvo, const float* __restrict__ a2_Wg,
               const float* __restrict__ a2_bg,  const float* __restrict__ a2_Wd,
               const float* __restrict__ f_Wvh,  const float* __restrict__ f_Ws,
               const int* __restrict__ idx_focal,
               float* __restrict__ out, int F)
{
  extern __shared__ char smraw[];
  SM& S = *reinterpret_cast<SM*>(smraw);
  const int tid = threadIdx.x;
  const int g = tid >> 3;    // channel group 0..31
  const int p = tid & 7;     // row pair     0..7
  const int row0 = blockIdx.x * R;

  if (tid < R) {
    const int row = row0 + tid;
    S.nidx[tid] = (row < F) ? idx_focal[row] : 0;
  }
  __syncthreads();

  if (tid < 3 * R) {
    const int rr = tid / 3, i = tid % 3;
    const int row = row0 + rr;
    const int n = S.nidx[rr];
    const float pv = (row < F) ? pos[(size_t)row * 3 + i] : 0.f;
    S.rp[i][rr] = pv - pos_compose[(size_t)n * 3 + i];
  }

  // gather into packed layout: thread tid = channel c; element (c,rr) lives at
  // float4[c>>1][rr>>1] component (c&1)*2 + (rr&1)
  for (int rr = 0; rr < R; ++rr) {
    const size_t n = (size_t)S.nidx[rr];
    reinterpret_cast<float*>(&S.ss[tid >> 1][rr >> 1])[(tid & 1) * 2 + (rr & 1)] =
        __ldg(&h_sca[n * 256 + tid]);
    if (tid < 192) {
      const int comp = tid % 3, c = tid / 3;
      reinterpret_cast<float*>(&S.sv[comp][c >> 1][rr >> 1])[(c & 1) * 2 + (rr & 1)] =
          __ldg(&h_vec[n * 192 + tid]);
    }
  }
  __syncthreads();

  // ================= g1: gv_perceptron =================
  matvec_v<128, 64, true>(g1_Wvh, S.sv, S.sh, S.sn, g, p);
  __syncthreads();
  matvec_s2<128, 128, 256>(g1_Ws, S.sn, S.ss, S.so, g, p);
  __syncthreads();
  gated_outv<128, 128, 128>(g1_Wvo, g1_Wg, g1_bg, S.sh, S.so, S.sv, g, p);
  scalar_act<128, true>(S.so, S.ss, g, p);
  __syncthreads();
  matvec_v<128, 128, false>(g1_Wd, S.sv, S.sh, S.sn, g, p);
  __syncthreads();
  vnleaky_ew<128>(S.sv, S.sh, g, p);
  __syncthreads();

  // ================= g2: gv_linear =================
  matvec_v<128, 128, true>(g2_Wvh, S.sv, S.sh, S.sn, g, p);
  __syncthreads();
  matvec_s2<128, 128, 128>(g2_Ws, S.sn, S.ss, S.so, g, p);
  __syncthreads();
  gated_outv<128, 128, 128>(g2_Wvo, g2_Wg, g2_bg, S.sh, S.so, S.sv, g, p);
  scalar_act<128, false>(S.so, S.ss, g, p);
  __syncthreads();

  // ================= a1: gv_perceptron =================
  matvec_v<256, 128, true>(a1_Wvh, S.sv, S.sh, S.sn, g, p);
  __syncthreads();
  matvec_s2<128, 256, 128>(a1_Ws, S.sn, S.ss, S.so, g, p);
  __syncthreads();
  gated_outv<256, 256, 128>(a1_Wvo, a1_Wg, a1_bg, S.sh, S.so, S.sv, g, p);
  scalar_act<128, true>(S.so, S.ss, g, p);
  __syncthreads();
  matvec_v<256, 256, false>(a1_Wd, S.sv, S.sh, S.sn, g, p);
  __syncthreads();
  vnleaky_ew<256>(S.sv, S.sh, g, p);
  __syncthreads();

  // ===== split: inner = <x_vec2 (sv ch 128..255), relpos> -> ss ch 128..255
  {
    const u64 rp0 = ld2(&S.rp[0][2 * p]);
    const u64 rp1 = ld2(&S.rp[1][2 * p]);
    const u64 rp2 = ld2(&S.rp[2][2 * p]);
#pragma unroll
    for (int j = 0; j < 4; ++j) {
      const int o = g + G * j;
      u64 acc = fmul2(uget(S.sv[0], 128 + o, p), rp0);
      acc = ffma2(uget(S.sv[1], 128 + o, p), rp1, acc);
      acc = ffma2(uget(S.sv[2], 128 + o, p), rp2, acc);
      uset(S.ss, 128 + o, p, acc);
    }
  }
  __syncthreads();

  // ================= a2: gv_perceptron =================
  matvec_v<128, 128, true>(a2_Wvh, S.sv, S.sh, S.sn, g, p);
  __syncthreads();
  matvec_s2<128, 128, 256>(a2_Ws, S.sn, S.ss, S.so, g, p);
  __syncthreads();
  gated_outv<128, 128, 128>(a2_Wvo, a2_Wg, a2_bg, S.sh, S.so, S.sv, g, p);
  scalar_act<128, true>(S.so, S.ss, g, p);
  __syncthreads();
  matvec_v<128, 128, false>(a2_Wd, S.sv, S.sh, S.sn, g, p);
  __syncthreads();
  vnleaky_ew<128>(S.sv, S.sh, g, p);
  __syncthreads();

  // ================= final =================
  matvec_v<128, 128, true>(f_Wvh, S.sv, S.sh, S.sn, g, p);
  __syncthreads();
  {
    u64 acc = 0ull;
#pragma unroll
    for (int kk = 0; kk < 8; ++kk) {
      const int k = g * 8 + kk;
      const u64 xv = (k < 128) ? uget(S.sn, k, p) : uget(S.ss, k - 128, p);
      acc = ffma2(dup2(__ldg(&f_Ws[k])), xv, acc);
    }
    uset(S.so, g, p, acc);
  }
  __syncthreads();
  if (tid < R) {
    const int row = row0 + tid;
    float acc = 0.f;
#pragma unroll
    for (int gg = 0; gg < G; ++gg)
      acc += reinterpret_cast<float*>(&S.so[gg >> 1][tid >> 1])[(gg & 1) * 2 + (tid & 1)];
    if (row < F) out[row] = acc;
  }
}

extern "C" void kernel_launch(void* const* d_in, const int* in_sizes, int n_in,
                              void* d_out, int out_size)
{
  const float* h_sca       = (const float*)d_in[0];
  const float* h_vec       = (const float*)d_in[1];
  const float* pos_compose = (const float*)d_in[2];
  const float* pos         = (const float*)d_in[3];
  const float* g1_Wvh = (const float*)d_in[4];
  const float* g1_Ws  = (const float*)d_in[5];
  const float* g1_Wvo = (const float*)d_in[6];
  const float* g1_Wg  = (const float*)d_in[7];
  const float* g1_bg  = (const float*)d_in[8];
  const float* g1_Wd  = (const float*)d_in[9];
  const float* g2_Wvh = (const float*)d_in[10];
  const float* g2_Ws  = (const float*)d_in[11];
  const float* g2_Wvo = (const float*)d_in[12];
  const float* g2_Wg  = (const float*)d_in[13];
  const float* g2_bg  = (const float*)d_in[14];
  const float* a1_Wvh = (const float*)d_in[15];
  const float* a1_Ws  = (const float*)d_in[16];
  const float* a1_Wvo = (const float*)d_in[17];
  const float* a1_Wg  = (const float*)d_in[18];
  const float* a1_bg  = (const float*)d_in[19];
  const float* a1_Wd  = (const float*)d_in[20];
  const float* a2_Wvh = (const float*)d_in[21];
  const float* a2_Ws  = (const float*)d_in[22];
  const float* a2_Wvo = (const float*)d_in[23];
  const float* a2_Wg  = (const float*)d_in[24];
  const float* a2_bg  = (const float*)d_in[25];
  const float* a2_Wd  = (const float*)d_in[26];
  const float* f_Wvh  = (const float*)d_in[27];
  const float* f_Ws   = (const float*)d_in[28];
  const int*   idx_focal = (const int*)d_in[29];

  const int F = in_sizes[3] / 3;   // pos is (F, 3)
  const int grid = (F + R - 1) / R;

  cudaFuncSetAttribute(pe_kernel, cudaFuncAttributeMaxDynamicSharedMemorySize,
                       (int)sizeof(SM));

  pe_kernel<<<grid, NT, sizeof(SM)>>>(
      h_sca, h_vec, pos_compose, pos,
      g1_Wvh, g1_Ws, g1_Wvo, g1_Wg, g1_bg, g1_Wd,
      g2_Wvh, g2_Ws, g2_Wvo, g2_Wg, g2_bg,
      a1_Wvh, a1_Ws, a1_Wvo, a1_Wg, a1_bg, a1_Wd,
      a2_Wvh, a2_Ws, a2_Wvo, a2_Wg, a2_bg, a2_Wd,
      f_Wvh, f_Ws, idx_focal,
      (float*)d_out, F);
}